// round 16
// baseline (speedup 1.0000x reference)
#include <cuda_runtime.h>
#include <cuda_fp16.h>
#include <cstdint>

// ---------------- problem constants ----------------
#define NN 15000          // nodes
#define NE 60000          // edges
#define ND 64             // NODE_DIM
#define HD 64             // HID
#define ED 33             // EDGE_DIM
#define CT 4160           // 65*64 real columns of M / T
#define CTP 4224          // padded column stride (33 * 128)
#define NTP 528           // CTP / 8 (column tiles of 8)

typedef unsigned long long ull;

__device__ __forceinline__ ull ffma2(ull a, ull b, ull c) {
    ull d;
    asm("fma.rn.f32x2 %0, %1, %2, %3;" : "=l"(d) : "l"(a), "l"(b), "l"(c));
    return d;
}
__device__ __forceinline__ ull dup2(float x) {
    ull d;
    asm("mov.b64 %0, {%1, %1};" : "=l"(d) : "f"(x));
    return d;
}
__device__ __forceinline__ ull pack2(float a, float b) {
    ull d;
    asm("mov.b64 %0, {%1, %2};" : "=l"(d) : "f"(a), "f"(b));
    return d;
}
__device__ __forceinline__ float lo2(ull a) { return __uint_as_float((unsigned)a); }
__device__ __forceinline__ float hi2(ull a) { return __uint_as_float((unsigned)(a >> 32)); }
// fp16 mma m16n8k16, fp32 accumulate
__device__ __forceinline__ void mma_f16(float* d, const uint4 a, const uint2 b) {
    asm("mma.sync.aligned.m16n8k16.row.col.f32.f16.f16.f32 "
        "{%0,%1,%2,%3}, {%4,%5,%6,%7}, {%8,%9}, {%0,%1,%2,%3};"
        : "+f"(d[0]), "+f"(d[1]), "+f"(d[2]), "+f"(d[3])
        : "r"(a.x), "r"(a.y), "r"(a.z), "r"(a.w), "r"(b.x), "r"(b.y));
}

// ---------------- device scratch (zero-init; consumers restore zeros) ----------------
__device__ float  g_xf[NN * ND];            // fp32 node features (k_final)
__device__ __half g_xfh[NN * ND];           // fp16 copy (gemm A)
__device__ float  g_h[NE * HD];
__device__ __half g_Mfh[4 * NTP * 128];     // B fp16 fragment order; padded cols stay 0
__device__ __half g_Th[(size_t)NN * CTP];   // per-node tensor, fp16 (126 MB)
__device__ float  g_sums[NN * HD];
__device__ int    g_dcnt[NN];
__device__ int    g_hist[NN];
__device__ int    g_off[NN + 1];
__device__ int    g_cursor[NN];
__device__ int    g_sorted[NE];

// ---------------- L0: Mfh build + node features + degree hists ----------------
#define NB_M    1040     // ceil(ND*CT/256)
#define NB_NODE 1875
#define NB_HIST 235
__global__ void k_prepA(const float* __restrict__ x,
                        const int* __restrict__ inp, const int* __restrict__ outp,
                        const float* __restrict__ in_emb, const float* __restrict__ out_emb,
                        const int* __restrict__ eidx,
                        const float* __restrict__ w2, const float* __restrict__ b2) {
    int b = blockIdx.x;
    int tid = threadIdx.x;
    if (b < NB_M) {                          // build Mfh (fp16 fragment layout)
        int idx = b * 256 + tid;
        if (idx >= ND * CT) return;
        int i = idx / CT;                    // k row 0..63
        int col = idx - i * CT;
        int j = col >> 6;
        int o = col & 63;
        float v = (j < 64) ? w2[j * 4096 + i * 64 + o] : b2[i * 64 + o];
        int kk16 = i >> 4, kc = i & 15;
        int reg = kc >> 3, c = (kc & 7) >> 1, hl = kc & 1;
        int lane = (col & 7) * 4 + c;
        g_Mfh[(((kk16 * NTP + (col >> 3)) * 32 + lane) * 2 + reg) * 2 + hl] = __float2half(v);
        return;
    }
    if (b < NB_M + NB_NODE) {                // node features (fp32 + fp16)
        int w = tid >> 5, l = tid & 31;
        int n = (b - NB_M) * 8 + w;
        if (n >= NN) return;
        float v0 = x[n * 32 + l];
        float v1 = (l < 16) ? in_emb[inp[n] * 16 + l]
                            : out_emb[outp[n] * 16 + (l - 16)];
        g_xf[n * 64 + l] = v0;
        g_xf[n * 64 + 32 + l] = v1;
        g_xfh[n * 64 + l] = __float2half(v0);
        g_xfh[n * 64 + 32 + l] = __float2half(v1);
        return;
    }
    int e = (b - NB_M - NB_NODE) * 256 + tid;
    if (e >= NE) return;
    atomicAdd(&g_hist[eidx[e]], 1);
    atomicAdd(&g_dcnt[eidx[NE + e]], 1);
}

// ---------------- L1: edge MLP, 2 edges/warp for ILP (32 edges/block) ----------------
__global__ void k_prepB(const int* __restrict__ e_nt, const int* __restrict__ e_np,
                        const float* __restrict__ e_sc,
                        const float* __restrict__ nt_emb, const float* __restrict__ np_emb,
                        const float* __restrict__ w1, const float* __restrict__ b1) {
    __shared__ float w1s[ED * 64];
    __shared__ float b1s[64];
    __shared__ float eas[16][34];
    int tid = threadIdx.x;
    for (int i = tid; i < ED * 64; i += 256) w1s[i] = w1[i];
    if (tid < 64) b1s[tid] = b1[tid];
    __syncthreads();
    int w = tid >> 5, l = tid & 31;
#pragma unroll
    for (int pass = 0; pass < 2; pass++) {
        int e0 = (blockIdx.x * 2 + pass) * 16 + 2 * w;   // exact: 1875*32 == NE
        int e1 = e0 + 1;
        if (l < 16) {
            eas[2 * w][l]     = nt_emb[e_nt[e0] * 16 + l];
            eas[2 * w + 1][l] = nt_emb[e_nt[e1] * 16 + l];
        } else {
            eas[2 * w][l]     = np_emb[e_np[e0] * 16 + (l - 16)];
            eas[2 * w + 1][l] = np_emb[e_np[e1] * 16 + (l - 16)];
        }
        if (l == 0) { eas[2 * w][32] = e_sc[e0]; eas[2 * w + 1][32] = e_sc[e1]; }
        __syncwarp();
        int o0 = l, o1 = l + 32;
        float a0 = b1s[o0], a1 = b1s[o1];
        float a2 = a0, a3 = a1;
#pragma unroll
        for (int k = 0; k < ED; k++) {
            float v0 = eas[2 * w][k];
            float v1 = eas[2 * w + 1][k];
            float w0 = w1s[k * 64 + o0];
            float w1v = w1s[k * 64 + o1];
            a0 = fmaf(v0, w0, a0);
            a1 = fmaf(v0, w1v, a1);
            a2 = fmaf(v1, w0, a2);
            a3 = fmaf(v1, w1v, a3);
        }
        g_h[e0 * 64 + o0] = fmaxf(a0, 0.f);
        g_h[e0 * 64 + o1] = fmaxf(a1, 0.f);
        g_h[e1 * 64 + o0] = fmaxf(a2, 0.f);
        g_h[e1 * 64 + o1] = fmaxf(a3, 0.f);
        __syncwarp();
    }
}

// ---------------- L2: fp16 MMA GEMM  T = xf @ M (fp16 out) ----------------
#define AS_B32 (4 * 8 * 128)            // 4096 b32 = 16 KB
__global__ __launch_bounds__(256) void k_gemm() {
    extern __shared__ uint32_t As32[];
    int tid = threadIdx.x;
    int c0 = blockIdx.x * 64;
    int r0 = blockIdx.y * 128;

#pragma unroll
    for (int t = 0; t < 2; t++) {
        int unit = t * 256 + tid;
        int m = unit >> 2, kk16 = unit & 3;
        int row = r0 + m;
        uint4 lo = make_uint4(0, 0, 0, 0), hi = lo;
        if (row < NN) {
            const uint4* src = (const uint4*)(g_xfh + row * 64 + kk16 * 16);
            lo = src[0];
            hi = src[1];
        }
        int mm = m & 15, mt = m >> 4;
        int r = mm & 7, hs = mm >> 3;
        uint32_t* base = As32 + (kk16 * 8 + mt) * 128;
        uint32_t lov[4] = {lo.x, lo.y, lo.z, lo.w};
        uint32_t hiv[4] = {hi.x, hi.y, hi.z, hi.w};
#pragma unroll
        for (int c = 0; c < 4; c++) {
            int lpos = (r * 4 + c) ^ kk16;
            base[lpos * 4 + hs] = lov[c];
            base[lpos * 4 + 2 + hs] = hiv[c];
        }
    }
    __syncthreads();

    int warp = tid >> 5, lane = tid & 31;
    int wm = warp & 3;
    int wn = warp >> 2;
    int r = lane >> 2, c = lane & 3;
    int nt0 = (c0 >> 3) + wn * 4;
    const uint2* Bf = (const uint2*)g_Mfh;

    float acc[2][4][4];
#pragma unroll
    for (int i = 0; i < 2; i++)
#pragma unroll
        for (int j = 0; j < 4; j++)
#pragma unroll
            for (int q = 0; q < 4; q++) acc[i][j][q] = 0.f;

#pragma unroll
    for (int kk16 = 0; kk16 < 4; kk16++) {
        uint4 a[2];
#pragma unroll
        for (int i = 0; i < 2; i++)
            a[i] = *(const uint4*)&As32[(kk16 * 8 + (wm * 2 + i)) * 128 + (lane ^ kk16) * 4];
        uint2 b[4];
#pragma unroll
        for (int j = 0; j < 4; j++)
            b[j] = Bf[(kk16 * NTP + nt0 + j) * 32 + lane];
#pragma unroll
        for (int i = 0; i < 2; i++)
#pragma unroll
            for (int j = 0; j < 4; j++)
                mma_f16(acc[i][j], a[i], b[j]);
    }

#pragma unroll
    for (int i = 0; i < 2; i++) {
        int rb = r0 + wm * 32 + i * 16 + r;
#pragma unroll
        for (int j = 0; j < 4; j++) {
            int col = c0 + wn * 32 + j * 8 + c * 2;
            if (rb < NN)
                *(__half2*)&g_Th[(size_t)rb * CTP + col] =
                    __floats2half2_rn(acc[i][j][0], acc[i][j][1]);
            if (rb + 8 < NN)
                *(__half2*)&g_Th[(size_t)(rb + 8) * CTP + col] =
                    __floats2half2_rn(acc[i][j][2], acc[i][j][3]);
        }
    }
}

// ---------------- L3 (PROFILED): CSR scan, blocked (1000x15), 2 barriers ----------------
__global__ void k_scan() {
    __shared__ int warp_sums[32];
    int tid = threadIdx.x;
    int lane = tid & 31, wid = tid >> 5;
    int base = tid * 15;                   // threads 0..999 cover exactly NN
    int v[15];
    int tot = 0;
    if (base < NN) {
#pragma unroll
        for (int i = 0; i < 15; i++) {
            int xx = g_hist[base + i];
            g_hist[base + i] = 0;          // restore zero for next replay
            tot += xx;
            v[i] = tot;                    // thread-local inclusive
        }
    }
    int xv = tot;
#pragma unroll
    for (int d = 1; d < 32; d <<= 1) {
        int y = __shfl_up_sync(0xffffffffu, xv, d);
        if (lane >= d) xv += y;
    }
    if (lane == 31) warp_sums[wid] = xv;
    __syncthreads();
    if (tid < 32) {
        int w = warp_sums[tid];
#pragma unroll
        for (int d = 1; d < 32; d <<= 1) {
            int y = __shfl_up_sync(0xffffffffu, w, d);
            if (tid >= d) w += y;
        }
        warp_sums[tid] = w;
    }
    __syncthreads();
    int tbase = (xv - tot) + ((wid > 0) ? warp_sums[wid - 1] : 0);
    if (tid == 0) g_off[0] = 0;
    if (base < NN) {
#pragma unroll
        for (int i = 0; i < 15; i++) {
            int incl = tbase + v[i];
            g_off[base + i + 1] = incl;
            int cnt = v[i] - (i ? v[i - 1] : 0);
            g_cursor[base + i] = incl - cnt;
        }
    }
}

// ---------------- L4: parallel scatter of edge ids ----------------
__global__ void k_scatter(const int* __restrict__ eidx) {
    int e = blockIdx.x * blockDim.x + threadIdx.x;
    if (e >= NE) return;
    int pos = atomicAdd(&g_cursor[eidx[e]], 1);
    g_sorted[pos] = e;
}

// ---------------- L5: per-src-node edge apply (fp16 T, wide staging) ----------------
__global__ void k_edge_apply(const int* __restrict__ eidx) {
    __shared__ __align__(16) float ts[CT];
    __shared__ ull hd[8][64];
    __shared__ int dsts[8];
    int n = blockIdx.x;
    int beg = g_off[n], end = g_off[n + 1];
    if (beg == end) return;
    int tid = threadIdx.x;
    const uint4* Tp = (const uint4*)(g_Th + (size_t)n * CTP);
    float2* tsp2 = (float2*)ts;
    for (int i = tid; i < CT / 8; i += 128) {
        uint4 v = Tp[i];
        tsp2[i * 4 + 0] = __half22float2(*(const __half2*)&v.x);
        tsp2[i * 4 + 1] = __half22float2(*(const __half2*)&v.y);
        tsp2[i * 4 + 2] = __half22float2(*(const __half2*)&v.z);
        tsp2[i * 4 + 3] = __half22float2(*(const __half2*)&v.w);
    }
    __syncthreads();

    int q = tid >> 4;
    int l16 = tid & 15;
    int o = l16 * 4;
    const ulonglong2* ts2 = (const ulonglong2*)ts;

    for (int p = beg; p < end; p += 8) {
        int idx = p + q;
        int e = -1;
        if (idx < end) {
            e = g_sorted[idx];
            const float* hp = g_h + e * 64;
#pragma unroll
            for (int t = 0; t < 4; t++) hd[q][o + t] = dup2(hp[o + t]);
            if (l16 == 0) dsts[q] = eidx[NE + e];
        }
        __syncthreads();
        if (e >= 0) {
            ull acc0 = *(const ull*)&ts[4096 + o];
            ull acc1 = *(const ull*)&ts[4096 + o + 2];
#pragma unroll 16
            for (int j = 0; j < 64; j++) {
                ull h2 = hd[q][j];
                ulonglong2 t4 = ts2[j * 16 + l16];
                acc0 = ffma2(h2, t4.x, acc0);
                acc1 = ffma2(h2, t4.y, acc1);
            }
            int dst = dsts[q];
            float* sp = g_sums + dst * 64 + o;
            atomicAdd(sp + 0, lo2(acc0));
            atomicAdd(sp + 1, hi2(acc0));
            atomicAdd(sp + 2, lo2(acc1));
            atomicAdd(sp + 3, hi2(acc1));
        }
        __syncthreads();
    }
}

// ---------------- L6: scatter-mean + root + ReLU + 4 heads (ffma2) ----------------
// smem: rwp float2[64*32] (pairs (o,o+32)) | cb[64] | Wc[64*240] | bc[240] | stage[8*128]
__global__ void k_final(const float* __restrict__ root_w, const float* __restrict__ conv_b,
                        const float* __restrict__ wsu, const float* __restrict__ bsu,
                        const float* __restrict__ wnt, const float* __restrict__ bnt,
                        const float* __restrict__ wtg, const float* __restrict__ btg,
                        const float* __restrict__ wpr, const float* __restrict__ bpr,
                        float* __restrict__ out) {
    extern __shared__ float sm[];
    float* rwp = sm;                 // 4096 floats (2048 float2 pairs)
    float* cb = rwp + 4096;          // 64
    float* Wc = cb + 64;             // 64*240
    float* bc = Wc + 64 * 240;       // 240
    float* stage = bc + 240;         // 8 * 128
    int tid = threadIdx.x;
    for (int i = tid; i < 2048; i += 256) {
        int r = i >> 5, o = i & 31;
        ((float2*)rwp)[i] = make_float2(root_w[r * 64 + o], root_w[r * 64 + o + 32]);
    }
    if (tid < 64) cb[tid] = conv_b[tid];
    for (int i = tid; i < 64 * 16; i += 256)  { int r = i >> 4, c = i & 15;  Wc[r * 240 + c]       = wsu[i]; }
    for (int i = tid; i < 64 * 32; i += 256)  { int r = i >> 5, c = i & 31;  Wc[r * 240 + 16 + c]  = wnt[i]; }
    for (int i = tid; i < 64 * 64; i += 256)  { int r = i >> 6, c = i & 63;  Wc[r * 240 + 48 + c]  = wtg[i]; }
    for (int i = tid; i < 64 * 128; i += 256) { int r = i >> 7, c = i & 127; Wc[r * 240 + 112 + c] = wpr[i]; }
    if (tid < 16)       bc[tid] = bsu[tid];
    else if (tid < 48)  bc[tid] = bnt[tid - 16];
    else if (tid < 112) bc[tid] = btg[tid - 48];
    else if (tid < 240) bc[tid] = bpr[tid - 112];
    __syncthreads();

    int w = tid >> 5, l = tid & 31;
    float* xs = stage + w * 128;
    float* os = xs + 64;

#pragma unroll
    for (int pass = 0; pass < 8; pass++) {
        int n = blockIdx.x * 64 + pass * 8 + w;
        if (n >= NN) break;
        xs[l] = g_xf[n * 64 + l];
        xs[l + 32] = g_xf[n * 64 + 32 + l];
        __syncwarp();

        float inv = 1.f / fmaxf((float)g_dcnt[n], 1.f);
        if (l == 0) g_dcnt[n] = 0;                          // restore zero
        float sv0 = g_sums[n * 64 + l];
        float sv1 = g_sums[n * 64 + 32 + l];
        g_sums[n * 64 + l] = 0.f;                           // restore zeros
        g_sums[n * 64 + 32 + l] = 0.f;

        ull racc = pack2(cb[l] + sv0 * inv, cb[l + 32] + sv1 * inv);
#pragma unroll 8
        for (int i = 0; i < 64; i++)
            racc = ffma2(dup2(xs[i]), *(const ull*)&((const float2*)rwp)[i * 32 + l], racc);
        os[l] = fmaxf(lo2(racc), 0.f);
        os[l + 32] = fmaxf(hi2(racc), 0.f);
        __syncwarp();

        ull hacc[4];
#pragma unroll
        for (int q = 0; q < 4; q++) {
            int t = l + 32 * q;
            hacc[q] = (t < 120) ? pack2(bc[2 * t], bc[2 * t + 1]) : 0ull;
        }
#pragma unroll 8
        for (int i = 0; i < 64; i++) {
            ull osd = dup2(os[i]);
            const float2* wr = (const float2*)&Wc[i * 240];
#pragma unroll
            for (int q = 0; q < 4; q++) {
                int t = l + 32 * q;
                if (t < 120) hacc[q] = ffma2(osd, *(const ull*)&wr[t], hacc[q]);
            }
        }
#pragma unroll
        for (int q = 0; q < 4; q++) {
            int t = l + 32 * q;
            if (t < 120) {
                int col = 2 * t;
                float2 val = make_float2(lo2(hacc[q]), hi2(hacc[q]));
                if (col < 16)       *(float2*)&out[n * 16 + col] = val;
                else if (col < 48)  *(float2*)&out[240000  + n * 32  + (col - 16)]  = val;
                else if (col < 112) *(float2*)&out[720000  + n * 64  + (col - 48)]  = val;
                else                *(float2*)&out[1680000 + n * 128 + (col - 112)] = val;
            }
        }
        __syncwarp();
    }
}

// ---------------- launch ----------------
extern "C" void kernel_launch(void* const* d_in, const int* in_sizes, int n_in,
                              void* d_out, int out_size) {
    const float* x        = (const float*)d_in[0];
    const int*   input_np = (const int*)  d_in[1];
    const int*   output_np= (const int*)  d_in[2];
    const int*   edge_idx = (const int*)  d_in[3];
    const int*   edge_nt  = (const int*)  d_in[4];
    const int*   edge_np  = (const int*)  d_in[5];
    const float* edge_sc  = (const float*)d_in[6];
    const float* in_emb   = (const float*)d_in[7];
    const float* out_emb  = (const float*)d_in[8];
    const float* enp_emb  = (const float*)d_in[9];
    const float* ent_emb  = (const float*)d_in[10];
    const float* w1       = (const float*)d_in[11];
    const float* b1       = (const float*)d_in[12];
    const float* w2       = (const float*)d_in[13];
    const float* b2       = (const float*)d_in[14];
    const float* root_w   = (const float*)d_in[15];
    const float* conv_b   = (const float*)d_in[16];
    const float* wsu      = (const float*)d_in[17];
    const float* bsu      = (const float*)d_in[18];
    const float* wnt      = (const float*)d_in[19];
    const float* bnt      = (const float*)d_in[20];
    const float* wtg      = (const float*)d_in[21];
    const float* btg      = (const float*)d_in[22];
    const float* wpr      = (const float*)d_in[23];
    const float* bpr      = (const float*)d_in[24];
    float* out = (float*)d_out;

    const int smem_gemm  = AS_B32 * 4;                                     // 16384 B
    const int smem_final = (4096 + 64 + 64 * 240 + 240 + 8 * 128) * 4;     // 83136 B
    cudaFuncSetAttribute(k_gemm,  cudaFuncAttributeMaxDynamicSharedMemorySize, smem_gemm);
    cudaFuncSetAttribute(k_final, cudaFuncAttributeMaxDynamicSharedMemorySize, smem_final);

    k_prepA<<<NB_M + NB_NODE + NB_HIST, 256>>>(x, input_np, output_np,     // idx 0
            in_emb, out_emb, edge_idx, w2, b2);
    k_prepB<<<NE / 32, 256>>>(edge_nt, edge_np, edge_sc,                   // idx 1
            ent_emb, enp_emb, w1, b1);
    dim3 ggrid(CTP / 64, (NN + 127) / 128);
    k_gemm<<<ggrid, 256, smem_gemm>>>();                                   // idx 2
    k_scan<<<1, 1024>>>();                                                 // idx 3 (profiled)
    k_scatter<<<(NE + 255) / 256, 256>>>(edge_idx);                        // idx 4
    k_edge_apply<<<NN, 128>>>(edge_idx);                                   // idx 5
    k_final<<<(NN + 63) / 64, 256, smem_final>>>(root_w, conv_b,           // idx 6
            wsu, bsu, wnt, bnt, wtg, btg, wpr, bpr, out);
}

// round 17
// speedup vs baseline: 1.0193x; 1.0193x over previous
#include <cuda_runtime.h>
#include <cuda_fp16.h>
#include <cstdint>

// ---------------- problem constants ----------------
#define NN 15000          // nodes
#define NE 60000          // edges
#define ND 64             // NODE_DIM
#define HD 64             // HID
#define ED 33             // EDGE_DIM
#define CT 4160           // 65*64 real columns of M / T
#define CTP 4224          // padded column stride (33 * 128)
#define NTP 528           // CTP / 8 (column tiles of 8)

typedef unsigned long long ull;

__device__ __forceinline__ ull ffma2(ull a, ull b, ull c) {
    ull d;
    asm("fma.rn.f32x2 %0, %1, %2, %3;" : "=l"(d) : "l"(a), "l"(b), "l"(c));
    return d;
}
__device__ __forceinline__ ull dup2(float x) {
    ull d;
    asm("mov.b64 %0, {%1, %1};" : "=l"(d) : "f"(x));
    return d;
}
__device__ __forceinline__ ull pack2(float a, float b) {
    ull d;
    asm("mov.b64 %0, {%1, %2};" : "=l"(d) : "f"(a), "f"(b));
    return d;
}
__device__ __forceinline__ float lo2(ull a) { return __uint_as_float((unsigned)a); }
__device__ __forceinline__ float hi2(ull a) { return __uint_as_float((unsigned)(a >> 32)); }
// fp16 mma m16n8k16, fp32 accumulate
__device__ __forceinline__ void mma_f16(float* d, const uint4 a, const uint2 b) {
    asm("mma.sync.aligned.m16n8k16.row.col.f32.f16.f16.f32 "
        "{%0,%1,%2,%3}, {%4,%5,%6,%7}, {%8,%9}, {%0,%1,%2,%3};"
        : "+f"(d[0]), "+f"(d[1]), "+f"(d[2]), "+f"(d[3])
        : "r"(a.x), "r"(a.y), "r"(a.z), "r"(a.w), "r"(b.x), "r"(b.y));
}
__device__ __forceinline__ uint4 ldsm_x4(uint32_t addr) {
    uint4 r;
    asm volatile("ldmatrix.sync.aligned.m8n8.x4.shared.b16 {%0,%1,%2,%3}, [%4];"
        : "=r"(r.x), "=r"(r.y), "=r"(r.z), "=r"(r.w) : "r"(addr));
    return r;
}

// ---------------- device scratch (zero-init; consumers restore zeros) ----------------
__device__ float  g_xf[NN * ND];            // fp32 node features (k_final)
__device__ __half g_xfh[NN * ND];           // fp16 copy (gemm A)
__device__ float  g_h[NE * HD];
__device__ __half g_Mfh[4 * NTP * 128];     // B fp16 fragment order; padded cols stay 0
__device__ __half g_Th[(size_t)NN * CTP];   // per-node tensor, fp16 (126 MB)
__device__ float  g_sums[NN * HD];
__device__ int    g_dcnt[NN];
__device__ int    g_hist[NN];
__device__ int    g_off[NN + 1];
__device__ int    g_cursor[NN];
__device__ int    g_sorted[NE];

// ---------------- L0: Mfh build + node features + degree hists ----------------
#define NB_M    1040     // ceil(ND*CT/256)
#define NB_NODE 1875
#define NB_HIST 235
__global__ void k_prepA(const float* __restrict__ x,
                        const int* __restrict__ inp, const int* __restrict__ outp,
                        const float* __restrict__ in_emb, const float* __restrict__ out_emb,
                        const int* __restrict__ eidx,
                        const float* __restrict__ w2, const float* __restrict__ b2) {
    int b = blockIdx.x;
    int tid = threadIdx.x;
    if (b < NB_M) {                          // build Mfh (fp16 fragment layout)
        int idx = b * 256 + tid;
        if (idx >= ND * CT) return;
        int i = idx / CT;                    // k row 0..63
        int col = idx - i * CT;
        int j = col >> 6;
        int o = col & 63;
        float v = (j < 64) ? w2[j * 4096 + i * 64 + o] : b2[i * 64 + o];
        int kk16 = i >> 4, kc = i & 15;
        int reg = kc >> 3, c = (kc & 7) >> 1, hl = kc & 1;
        int lane = (col & 7) * 4 + c;
        g_Mfh[(((kk16 * NTP + (col >> 3)) * 32 + lane) * 2 + reg) * 2 + hl] = __float2half(v);
        return;
    }
    if (b < NB_M + NB_NODE) {                // node features (fp32 + fp16)
        int w = tid >> 5, l = tid & 31;
        int n = (b - NB_M) * 8 + w;
        if (n >= NN) return;
        float v0 = x[n * 32 + l];
        float v1 = (l < 16) ? in_emb[inp[n] * 16 + l]
                            : out_emb[outp[n] * 16 + (l - 16)];
        g_xf[n * 64 + l] = v0;
        g_xf[n * 64 + 32 + l] = v1;
        g_xfh[n * 64 + l] = __float2half(v0);
        g_xfh[n * 64 + 32 + l] = __float2half(v1);
        return;
    }
    int e = (b - NB_M - NB_NODE) * 256 + tid;
    if (e >= NE) return;
    atomicAdd(&g_hist[eidx[e]], 1);
    atomicAdd(&g_dcnt[eidx[NE + e]], 1);
}

// ---------------- L1: edge MLP, 2 edges/warp for ILP (32 edges/block) ----------------
__global__ void k_prepB(const int* __restrict__ e_nt, const int* __restrict__ e_np,
                        const float* __restrict__ e_sc,
                        const float* __restrict__ nt_emb, const float* __restrict__ np_emb,
                        const float* __restrict__ w1, const float* __restrict__ b1) {
    __shared__ float w1s[ED * 64];
    __shared__ float b1s[64];
    __shared__ float eas[16][34];
    int tid = threadIdx.x;
    for (int i = tid; i < ED * 64; i += 256) w1s[i] = w1[i];
    if (tid < 64) b1s[tid] = b1[tid];
    __syncthreads();
    int w = tid >> 5, l = tid & 31;
#pragma unroll
    for (int pass = 0; pass < 2; pass++) {
        int e0 = (blockIdx.x * 2 + pass) * 16 + 2 * w;   // exact: 1875*32 == NE
        int e1 = e0 + 1;
        if (l < 16) {
            eas[2 * w][l]     = nt_emb[e_nt[e0] * 16 + l];
            eas[2 * w + 1][l] = nt_emb[e_nt[e1] * 16 + l];
        } else {
            eas[2 * w][l]     = np_emb[e_np[e0] * 16 + (l - 16)];
            eas[2 * w + 1][l] = np_emb[e_np[e1] * 16 + (l - 16)];
        }
        if (l == 0) { eas[2 * w][32] = e_sc[e0]; eas[2 * w + 1][32] = e_sc[e1]; }
        __syncwarp();
        int o0 = l, o1 = l + 32;
        float a0 = b1s[o0], a1 = b1s[o1];
        float a2 = a0, a3 = a1;
#pragma unroll
        for (int k = 0; k < ED; k++) {
            float v0 = eas[2 * w][k];
            float v1 = eas[2 * w + 1][k];
            float w0 = w1s[k * 64 + o0];
            float w1v = w1s[k * 64 + o1];
            a0 = fmaf(v0, w0, a0);
            a1 = fmaf(v0, w1v, a1);
            a2 = fmaf(v1, w0, a2);
            a3 = fmaf(v1, w1v, a3);
        }
        g_h[e0 * 64 + o0] = fmaxf(a0, 0.f);
        g_h[e0 * 64 + o1] = fmaxf(a1, 0.f);
        g_h[e1 * 64 + o0] = fmaxf(a2, 0.f);
        g_h[e1 * 64 + o1] = fmaxf(a3, 0.f);
        __syncwarp();
    }
}

// ---------------- L2: CSR scan, smem-staged, coalesced ----------------
__global__ void k_scan() {
    extern __shared__ int sh[];              // NN ints (60000 B)
    __shared__ int warp_sums[32];
    int tid = threadIdx.x;
    int lane = tid & 31, wid = tid >> 5;
    for (int i = tid; i < NN; i += 1024) { sh[i] = g_hist[i]; g_hist[i] = 0; }
    __syncthreads();
    int base = tid * 15;
    int tot = 0;
    int v[15];
    if (base < NN) {
#pragma unroll
        for (int i = 0; i < 15; i++) { tot += sh[base + i]; v[i] = tot; }
    }
    int xv = tot;
#pragma unroll
    for (int d = 1; d < 32; d <<= 1) {
        int y = __shfl_up_sync(0xffffffffu, xv, d);
        if (lane >= d) xv += y;
    }
    if (lane == 31) warp_sums[wid] = xv;
    __syncthreads();
    if (tid < 32) {
        int w = warp_sums[tid];
#pragma unroll
        for (int d = 1; d < 32; d <<= 1) {
            int y = __shfl_up_sync(0xffffffffu, w, d);
            if (tid >= d) w += y;
        }
        warp_sums[tid] = w;
    }
    __syncthreads();
    int tbase = (xv - tot) + ((wid > 0) ? warp_sums[wid - 1] : 0);
    if (base < NN) {
#pragma unroll
        for (int i = 0; i < 15; i++) sh[base + i] = v[i] + tbase;
    }
    __syncthreads();
    if (tid == 0) g_off[0] = 0;
    for (int i = tid; i < NN; i += 1024) {
        g_off[i + 1] = sh[i];
        g_cursor[i] = i ? sh[i - 1] : 0;     // exclusive prefix
    }
}

// ---------------- L3 (PROFILED): fp16 MMA GEMM with ldmatrix A ----------------
// Block tile 128m x 64n, K=64 (4 k16-steps). 256 threads = 8 warps (4m x 2n).
// A smem layout per kk16 (4096 B): 16B unit at  p*128 + (((m&3)*2+h)^(p&7))*16,
// p = m>>2, h = k-octet. Staging: 2x STS.128/thread (CF per quarter-warp phase).
// Fragments via ldmatrix.x4 (matrices 0..3 = a0..a3). B straight from g_Mfh.
#define AS_B32 (4 * 1024)               // 4096 b32 = 16 KB
__global__ __launch_bounds__(256) void k_gemm() {
    extern __shared__ uint32_t As32[];
    int tid = threadIdx.x;
    int c0 = blockIdx.x * 64;
    int r0 = blockIdx.y * 128;

    // stage A: unit = kk16*128 + m; 2 units/thread; 2 LDG.128 + 2 STS.128 each
#pragma unroll
    for (int t = 0; t < 2; t++) {
        int unit = t * 256 + tid;
        int kk16 = unit >> 7, m = unit & 127;
        int row = r0 + m;
        uint4 lo = make_uint4(0, 0, 0, 0), hi = lo;
        if (row < NN) {
            const uint4* src = (const uint4*)(g_xfh + row * 64 + kk16 * 16);
            lo = src[0];                    // k 0..7 of this octet-pair
            hi = src[1];                    // k 8..15
        }
        int p = m >> 2;
        int u0 = ((m & 3) * 2) ^ (p & 7);
        uint32_t* base = As32 + kk16 * 1024 + p * 32;
        *(uint4*)(base + u0 * 4) = lo;
        *(uint4*)(base + (u0 ^ 1) * 4) = hi;
    }
    __syncthreads();

    int warp = tid >> 5, lane = tid & 31;
    int wm = warp & 3;              // 4 m-groups of 32 rows
    int wn = warp >> 2;             // 2 n-groups of 32 cols
    int r = lane >> 2, c = lane & 3;
    int nt0 = (c0 >> 3) + wn * 4;
    const uint2* Bf = (const uint2*)g_Mfh;
    uint32_t as_base = (uint32_t)__cvta_generic_to_shared(As32);
    // ldmatrix per-lane source row/half
    int mr_off = lane & 15;         // row within 16-row tile
    int h = lane >> 4;              // k-octet select

    float acc[2][4][4];
#pragma unroll
    for (int i = 0; i < 2; i++)
#pragma unroll
        for (int j = 0; j < 4; j++)
#pragma unroll
            for (int q = 0; q < 4; q++) acc[i][j][q] = 0.f;

#pragma unroll
    for (int kk16 = 0; kk16 < 4; kk16++) {
        uint4 a[2];
#pragma unroll
        for (int i = 0; i < 2; i++) {
            int mr = wm * 32 + i * 16 + mr_off;
            int p = mr >> 2;
            int u = (((mr & 3) * 2 + h) ^ (p & 7));
            a[i] = ldsm_x4(as_base + kk16 * 4096 + p * 128 + u * 16);
        }
        uint2 b[4];
#pragma unroll
        for (int j = 0; j < 4; j++)
            b[j] = Bf[(kk16 * NTP + nt0 + j) * 32 + lane];
#pragma unroll
        for (int i = 0; i < 2; i++)
#pragma unroll
            for (int j = 0; j < 4; j++)
                mma_f16(acc[i][j], a[i], b[j]);
    }

#pragma unroll
    for (int i = 0; i < 2; i++) {
        int rb = r0 + wm * 32 + i * 16 + r;
#pragma unroll
        for (int j = 0; j < 4; j++) {
            int col = c0 + wn * 32 + j * 8 + c * 2;
            if (rb < NN)
                *(__half2*)&g_Th[(size_t)rb * CTP + col] =
                    __floats2half2_rn(acc[i][j][0], acc[i][j][1]);
            if (rb + 8 < NN)
                *(__half2*)&g_Th[(size_t)(rb + 8) * CTP + col] =
                    __floats2half2_rn(acc[i][j][2], acc[i][j][3]);
        }
    }
}

// ---------------- L4: parallel scatter of edge ids ----------------
__global__ void k_scatter(const int* __restrict__ eidx) {
    int e = blockIdx.x * blockDim.x + threadIdx.x;
    if (e >= NE) return;
    int pos = atomicAdd(&g_cursor[eidx[e]], 1);
    g_sorted[pos] = e;
}

// ---------------- L5: per-src-node edge apply (fp16 T, wide staging) ----------------
__global__ void k_edge_apply(const int* __restrict__ eidx) {
    __shared__ __align__(16) float ts[CT];
    __shared__ ull hd[8][64];
    __shared__ int dsts[8];
    int n = blockIdx.x;
    int beg = g_off[n], end = g_off[n + 1];
    if (beg == end) return;
    int tid = threadIdx.x;
    const uint4* Tp = (const uint4*)(g_Th + (size_t)n * CTP);
    float2* tsp2 = (float2*)ts;
    for (int i = tid; i < CT / 8; i += 128) {
        uint4 v = Tp[i];
        tsp2[i * 4 + 0] = __half22float2(*(const __half2*)&v.x);
        tsp2[i * 4 + 1] = __half22float2(*(const __half2*)&v.y);
        tsp2[i * 4 + 2] = __half22float2(*(const __half2*)&v.z);
        tsp2[i * 4 + 3] = __half22float2(*(const __half2*)&v.w);
    }
    __syncthreads();

    int q = tid >> 4;
    int l16 = tid & 15;
    int o = l16 * 4;
    const ulonglong2* ts2 = (const ulonglong2*)ts;

    for (int p = beg; p < end; p += 8) {
        int idx = p + q;
        int e = -1;
        if (idx < end) {
            e = g_sorted[idx];
            const float* hp = g_h + e * 64;
#pragma unroll
            for (int t = 0; t < 4; t++) hd[q][o + t] = dup2(hp[o + t]);
            if (l16 == 0) dsts[q] = eidx[NE + e];
        }
        __syncthreads();
        if (e >= 0) {
            ull acc0 = *(const ull*)&ts[4096 + o];
            ull acc1 = *(const ull*)&ts[4096 + o + 2];
#pragma unroll 16
            for (int j = 0; j < 64; j++) {
                ull h2 = hd[q][j];
                ulonglong2 t4 = ts2[j * 16 + l16];
                acc0 = ffma2(h2, t4.x, acc0);
                acc1 = ffma2(h2, t4.y, acc1);
            }
            int dst = dsts[q];
            float* sp = g_sums + dst * 64 + o;
            atomicAdd(sp + 0, lo2(acc0));
            atomicAdd(sp + 1, hi2(acc0));
            atomicAdd(sp + 2, lo2(acc1));
            atomicAdd(sp + 3, hi2(acc1));
        }
        __syncthreads();
    }
}

// ---------------- L6: scatter-mean + root + ReLU + 4 heads (ffma2) ----------------
__global__ void k_final(const float* __restrict__ root_w, const float* __restrict__ conv_b,
                        const float* __restrict__ wsu, const float* __restrict__ bsu,
                        const float* __restrict__ wnt, const float* __restrict__ bnt,
                        const float* __restrict__ wtg, const float* __restrict__ btg,
                        const float* __restrict__ wpr, const float* __restrict__ bpr,
                        float* __restrict__ out) {
    extern __shared__ float sm[];
    float* rwp = sm;                 // 4096 floats (2048 float2 pairs)
    float* cb = rwp + 4096;          // 64
    float* Wc = cb + 64;             // 64*240
    float* bc = Wc + 64 * 240;       // 240
    float* stage = bc + 240;         // 8 * 128
    int tid = threadIdx.x;
    for (int i = tid; i < 2048; i += 256) {
        int r = i >> 5, o = i & 31;
        ((float2*)rwp)[i] = make_float2(root_w[r * 64 + o], root_w[r * 64 + o + 32]);
    }
    if (tid < 64) cb[tid] = conv_b[tid];
    for (int i = tid; i < 64 * 16; i += 256)  { int r = i >> 4, c = i & 15;  Wc[r * 240 + c]       = wsu[i]; }
    for (int i = tid; i < 64 * 32; i += 256)  { int r = i >> 5, c = i & 31;  Wc[r * 240 + 16 + c]  = wnt[i]; }
    for (int i = tid; i < 64 * 64; i += 256)  { int r = i >> 6, c = i & 63;  Wc[r * 240 + 48 + c]  = wtg[i]; }
    for (int i = tid; i < 64 * 128; i += 256) { int r = i >> 7, c = i & 127; Wc[r * 240 + 112 + c] = wpr[i]; }
    if (tid < 16)       bc[tid] = bsu[tid];
    else if (tid < 48)  bc[tid] = bnt[tid - 16];
    else if (tid < 112) bc[tid] = btg[tid - 48];
    else if (tid < 240) bc[tid] = bpr[tid - 112];
    __syncthreads();

    int w = tid >> 5, l = tid & 31;
    float* xs = stage + w * 128;
    float* os = xs + 64;

#pragma unroll
    for (int pass = 0; pass < 8; pass++) {
        int n = blockIdx.x * 64 + pass * 8 + w;
        if (n >= NN) break;
        xs[l] = g_xf[n * 64 + l];
        xs[l + 32] = g_xf[n * 64 + 32 + l];
        __syncwarp();

        float inv = 1.f / fmaxf((float)g_dcnt[n], 1.f);
        if (l == 0) g_dcnt[n] = 0;                          // restore zero
        float sv0 = g_sums[n * 64 + l];
        float sv1 = g_sums[n * 64 + 32 + l];
        g_sums[n * 64 + l] = 0.f;                           // restore zeros
        g_sums[n * 64 + 32 + l] = 0.f;

        ull racc = pack2(cb[l] + sv0 * inv, cb[l + 32] + sv1 * inv);
#pragma unroll 8
        for (int i = 0; i < 64; i++)
            racc = ffma2(dup2(xs[i]), *(const ull*)&((const float2*)rwp)[i * 32 + l], racc);
        os[l] = fmaxf(lo2(racc), 0.f);
        os[l + 32] = fmaxf(hi2(racc), 0.f);
        __syncwarp();

        ull hacc[4];
#pragma unroll
        for (int q = 0; q < 4; q++) {
            int t = l + 32 * q;
            hacc[q] = (t < 120) ? pack2(bc[2 * t], bc[2 * t + 1]) : 0ull;
        }
#pragma unroll 8
        for (int i = 0; i < 64; i++) {
            ull osd = dup2(os[i]);
            const float2* wr = (const float2*)&Wc[i * 240];
#pragma unroll
            for (int q = 0; q < 4; q++) {
                int t = l + 32 * q;
                if (t < 120) hacc[q] = ffma2(osd, *(const ull*)&wr[t], hacc[q]);
            }
        }
#pragma unroll
        for (int q = 0; q < 4; q++) {
            int t = l + 32 * q;
            if (t < 120) {
                int col = 2 * t;
                float2 val = make_float2(lo2(hacc[q]), hi2(hacc[q]));
                if (col < 16)       *(float2*)&out[n * 16 + col] = val;
                else if (col < 48)  *(float2*)&out[240000  + n * 32  + (col - 16)]  = val;
                else if (col < 112) *(float2*)&out[720000  + n * 64  + (col - 48)]  = val;
                else                *(float2*)&out[1680000 + n * 128 + (col - 112)] = val;
            }
        }
        __syncwarp();
    }
}

// ---------------- launch ----------------
extern "C" void kernel_launch(void* const* d_in, const int* in_sizes, int n_in,
                              void* d_out, int out_size) {
    const float* x        = (const float*)d_in[0];
    const int*   input_np = (const int*)  d_in[1];
    const int*   output_np= (const int*)  d_in[2];
    const int*   edge_idx = (const int*)  d_in[3];
    const int*   edge_nt  = (const int*)  d_in[4];
    const int*   edge_np  = (const int*)  d_in[5];
    const float* edge_sc  = (const float*)d_in[6];
    const float* in_emb   = (const float*)d_in[7];
    const float* out_emb  = (const float*)d_in[8];
    const float* enp_emb  = (const float*)d_in[9];
    const float* ent_emb  = (const float*)d_in[10];
    const float* w1       = (const float*)d_in[11];
    const float* b1       = (const float*)d_in[12];
    const float* w2       = (const float*)d_in[13];
    const float* b2       = (const float*)d_in[14];
    const float* root_w   = (const float*)d_in[15];
    const float* conv_b   = (const float*)d_in[16];
    const float* wsu      = (const float*)d_in[17];
    const float* bsu      = (const float*)d_in[18];
    const float* wnt      = (const float*)d_in[19];
    const float* bnt      = (const float*)d_in[20];
    const float* wtg      = (const float*)d_in[21];
    const float* btg      = (const float*)d_in[22];
    const float* wpr      = (const float*)d_in[23];
    const float* bpr      = (const float*)d_in[24];
    float* out = (float*)d_out;

    const int smem_gemm  = AS_B32 * 4;                                     // 16384 B
    const int smem_scan  = NN * 4;                                         // 60000 B
    const int smem_final = (4096 + 64 + 64 * 240 + 240 + 8 * 128) * 4;     // 83136 B
    cudaFuncSetAttribute(k_gemm,  cudaFuncAttributeMaxDynamicSharedMemorySize, smem_gemm);
    cudaFuncSetAttribute(k_scan,  cudaFuncAttributeMaxDynamicSharedMemorySize, smem_scan);
    cudaFuncSetAttribute(k_final, cudaFuncAttributeMaxDynamicSharedMemorySize, smem_final);

    k_prepA<<<NB_M + NB_NODE + NB_HIST, 256>>>(x, input_np, output_np,     // idx 0
            in_emb, out_emb, edge_idx, w2, b2);
    k_prepB<<<NE / 32, 256>>>(edge_nt, edge_np, edge_sc,                   // idx 1
            ent_emb, enp_emb, w1, b1);
    k_scan<<<1, 1024, smem_scan>>>();                                      // idx 2
    dim3 ggrid(CTP / 64, (NN + 127) / 128);
    k_gemm<<<ggrid, 256, smem_gemm>>>();                                   // idx 3 (profiled)
    k_scatter<<<(NE + 255) / 256, 256>>>(edge_idx);                        // idx 4
    k_edge_apply<<<NN, 128>>>(edge_idx);                                   // idx 5
    k_final<<<(NN + 63) / 64, 256, smem_final>>>(root_w, conv_b,           // idx 6
            wsu, bsu, wnt, bnt, wtg, btg, wpr, bpr, out);
}